// round 13
// baseline (speedup 1.0000x reference)
#include <cuda_runtime.h>
#include <cuda_fp16.h>
#include <math.h>
#include <stdint.h>

#define S_LEN 256
#define BATCH 64
#define FEAT  256
#define HID   768
#define GATES 3072
#define TLEN  32
#define OUT_ENC_OFF (TLEN*BATCH*FEAT)
#define XM    (S_LEN*BATCH)

#define NB   64       // encoder blocks
#define DNB  16       // decoder blocks (fused: blockIdx 64..79)
#define DUPB 48
#define SROWS 72
#define UPB  12       // hidden units per encoder block
#define RPB  48       // gate rows per encoder block
#define WPAD 776

// xg stored TRANSPOSED: [t][gate_row][batch]
static __device__ float g_xg[(size_t)S_LEN*GATES*BATCH];
static __device__ __half g_xh[(size_t)XM*FEAT];
static __device__ __half g_whi[(size_t)GATES*FEAT];
static __device__ __half g_wlo[(size_t)GATES*FEAT];
static __device__ __half g_hh[2][BATCH*HID];
static __device__ float g_hd[2][HID];
static __device__ unsigned g_bar;
static __device__ unsigned g_bar2;

__device__ __forceinline__ float sigf(float x){
    return __fdividef(1.f, 1.f + __expf(-x));
}
__device__ __forceinline__ float tanhfast(float x){
    return 1.f - __fdividef(2.f, __expf(2.f*x) + 1.f);
}

__device__ __forceinline__ void mma_f16(float* c, const uint32_t* a, uint32_t b0, uint32_t b1){
    asm volatile(
        "mma.sync.aligned.m16n8k16.row.col.f32.f16.f16.f32 "
        "{%0,%1,%2,%3}, {%4,%5,%6,%7}, {%8,%9}, {%0,%1,%2,%3};"
        : "+f"(c[0]), "+f"(c[1]), "+f"(c[2]), "+f"(c[3])
        : "r"(a[0]), "r"(a[1]), "r"(a[2]), "r"(a[3]), "r"(b0), "r"(b1));
}
__device__ __forceinline__ void ldsm4(uint32_t* a, uint32_t addr){
    asm volatile("ldmatrix.sync.aligned.m8n8.x4.shared.b16 {%0,%1,%2,%3}, [%4];"
        : "=r"(a[0]), "=r"(a[1]), "=r"(a[2]), "=r"(a[3]) : "r"(addr));
}
__device__ __forceinline__ void bar_arrive(unsigned* p){
    asm volatile("red.release.gpu.global.add.u32 [%0], %1;" :: "l"(p), "r"(1u) : "memory");
}
__device__ __forceinline__ unsigned bar_poll(unsigned* p){
    unsigned v;
    asm volatile("ld.acquire.gpu.global.u32 %0, [%1];" : "=r"(v) : "l"(p) : "memory");
    return v;
}

__global__ void k_init() {
    int i = blockIdx.x*blockDim.x + threadIdx.x;
    if (i < BATCH*HID/2) ((uint32_t*)g_hh[0])[i] = 0u;
    if (i < HID) g_hd[0][i] = 0.f;
    if (i == 0) { g_bar = 0u; g_bar2 = 0u; }
}

__global__ void k_cvt1(const float* __restrict__ src, __half* __restrict__ dhi, int n) {
    int i = blockIdx.x*blockDim.x + threadIdx.x;
    if (i < n) dhi[i] = __float2half(src[i]);
}
__global__ void k_cvt2(const float* __restrict__ src,
                       __half* __restrict__ dhi, __half* __restrict__ dlo, int n) {
    int i = blockIdx.x*blockDim.x + threadIdx.x;
    if (i < n) {
        float v = src[i];
        __half hi = __float2half(v);
        dhi[i] = hi;
        dlo[i] = __float2half(v - __half2float(hi));
    }
}

// ---------------- tensor-core xg GEMM (single-buffer, ldsm-B) -------------
__global__ __launch_bounds__(256, 2) void k_xg_mma(
    const float* __restrict__ b1, const float* __restrict__ b2)
{
    extern __shared__ char smraw[];
    uint32_t xs_base = (uint32_t)__cvta_generic_to_shared(smraw);
    uint32_t ws_base = xs_base + 32768;
    float* sbias = (float*)(smraw + 98304);

    const int tid  = threadIdx.x;
    const int wid  = tid >> 5;
    const int lane = tid & 31;
    const int mw   = wid & 3;
    const int nw   = wid >> 2;
    const int bn   = blockIdx.x * 128;
    const int bm   = blockIdx.y * 128;
    const int l4 = lane >> 2;
    const int l2 = lane & 3;
    const int r  = lane & 15;
    const int seg = lane >> 4;
    const int bmid = lane >> 3;
    const int brow = lane & 7;

    if (tid < 128) sbias[tid] = b1[bn+tid] + b2[bn+tid];

    float acc[2][8][4];
#pragma unroll
    for (int mt = 0; mt < 2; mt++)
#pragma unroll
        for (int nt = 0; nt < 8; nt++)
#pragma unroll
            for (int j = 0; j < 4; j++) acc[mt][nt][j] = 0.f;

    for (int ph = 0; ph < 2; ph++) {
        __syncthreads();
#pragma unroll
        for (int i = 0; i < 8; i++) {
            int g = tid + i*256;
            int s = g & 15, row = g >> 4;
            uint32_t dst = xs_base + (uint32_t)(row*256 + ((s ^ (row&7))*16));
            const __half* src = g_xh + (size_t)(bm+row)*FEAT + ph*128 + s*8;
            asm volatile("cp.async.cg.shared.global [%0], [%1], 16;" :: "r"(dst), "l"(src));
        }
#pragma unroll
        for (int i = 0; i < 16; i++) {
            int g = tid + i*256;
            int s = g & 15, row = (g >> 4) & 127, pl = g >> 11;
            uint32_t dst = ws_base + (uint32_t)(pl*32768 + row*256 + ((s ^ (row&7))*16));
            const __half* src = (pl ? g_wlo : g_whi) + (size_t)(bn+row)*FEAT + ph*128 + s*8;
            asm volatile("cp.async.cg.shared.global [%0], [%1], 16;" :: "r"(dst), "l"(src));
        }
        asm volatile("cp.async.commit_group;");
        asm volatile("cp.async.wait_group 0;");
        __syncthreads();

#pragma unroll
        for (int ks = 0; ks < 8; ks++) {
            uint32_t ahi[2][4];
#pragma unroll
            for (int mt = 0; mt < 2; mt++) {
                uint32_t rowoff = (uint32_t)((mw*32 + mt*16 + r)*256);
                uint32_t coff = (uint32_t)((ks*32 + seg*16) ^ ((r&7)*16));
                ldsm4(ahi[mt], xs_base + rowoff + coff);
            }
#pragma unroll
            for (int nt = 0; nt < 8; nt++) {
                int wrow = nw*64 + nt*8 + brow;
                uint32_t baddr = ws_base + (uint32_t)((bmid>>1)*32768 + wrow*256
                                 + (((ks*2 + (bmid&1)) ^ brow)*16));
                uint32_t bf[4];
                ldsm4(bf, baddr);
#pragma unroll
                for (int mt = 0; mt < 2; mt++) {
                    mma_f16(acc[mt][nt], ahi[mt], bf[0], bf[1]);
                    mma_f16(acc[mt][nt], ahi[mt], bf[2], bf[3]);
                }
            }
        }
    }

#pragma unroll
    for (int mt = 0; mt < 2; mt++) {
#pragma unroll
        for (int nt = 0; nt < 8; nt++) {
            int nloc = nw*64 + nt*8 + 2*l2;
            int n0 = bn + nloc;
            int m0 = bm + mw*32 + mt*16 + l4;
            int t = m0 >> 6, b = m0 & 63;
            size_t base = (size_t)t*GATES*BATCH;
            float bi0 = sbias[nloc], bi1 = sbias[nloc+1];
            g_xg[base + (size_t)n0*BATCH + b]         = acc[mt][nt][0] + bi0;
            g_xg[base + (size_t)(n0+1)*BATCH + b]     = acc[mt][nt][1] + bi1;
            g_xg[base + (size_t)n0*BATCH + b + 8]     = acc[mt][nt][2] + bi0;
            g_xg[base + (size_t)(n0+1)*BATCH + b + 8] = acc[mt][nt][3] + bi1;
        }
    }
}

// ---------------- fused persistent kernel: encoder (blocks 0..63) +
//                  decoder (blocks 64..79, independent, overlapped) --------
__device__ __forceinline__ void load_xv(int t, int bx0,
                                        const int growx[3][2], float xv[3][2][2],
                                        const float* __restrict__ eb1,
                                        const float* __restrict__ eb2)
{
    if (t >= 258) return;
    if (t < 256) {
        const float* xg = g_xg + (size_t)t * GATES * BATCH;
#pragma unroll
        for (int nt = 0; nt < 3; nt++)
#pragma unroll
            for (int jj = 0; jj < 2; jj++) {
                const float* rowp = xg + (size_t)growx[nt][jj]*BATCH + bx0;
                xv[nt][jj][0] = __ldcg(rowp);
                xv[nt][jj][1] = __ldcg(rowp + 8);
            }
    } else {
        int l = t - 256;
#pragma unroll
        for (int nt = 0; nt < 3; nt++)
#pragma unroll
            for (int jj = 0; jj < 2; jj++) {
                float bb = __ldg(eb1 + l*GATES + growx[nt][jj]) +
                           __ldg(eb2 + l*GATES + growx[nt][jj]);
                xv[nt][jj][0] = bb;
                xv[nt][jj][1] = bb;
            }
    }
}

// Encoder: NB=64 blocks, 12 units (48 gate rows) each. Warps: mw=wid&3
// (batches 16mw..+15), nh=wid>>2 (rows nh*24..+23). Full K per warp — no
// partial-sum reduction. h staged in 3 double-buffered rounds of K=256.
__device__ void enc_path(
    const float* __restrict__ Whh, const float* __restrict__ eWih,
    const float* __restrict__ ebih, const float* __restrict__ ebhh,
    float* __restrict__ out, char* smraw)
{
    __half* Whi = (__half*)smraw;                      // 48*776
    __half* Wlo = Whi + RPB*WPAD;                      // 48*776
    __half* hsm = Wlo + RPB*WPAD;                      // 2 buf * 32768 B
    float* gs  = (float*)((char*)hsm + 65536);         // 48*66
    float* c_s = gs + RPB*66;                          // 768

    const int tid  = threadIdx.x;
    const int wid  = tid >> 5;
    const int lane = tid & 31;
    const int mw   = wid & 3;
    const int nh   = wid >> 2;
    const int u0   = blockIdx.x * UPB;

    for (int e = tid; e < RPB*HID; e += 256) {
        int rr = e / HID, k = e % HID;
        int grow = (rr/UPB)*HID + u0 + (rr%UPB);
        float w = Whh[(size_t)grow*HID + k];
        __half hi = __float2half(w);
        Whi[rr*WPAD + k] = hi;
        Wlo[rr*WPAD + k] = __float2half(w - __half2float(hi));
    }
    for (int e = tid; e < UPB*BATCH; e += 256) c_s[e] = 0.f;

    uint32_t hs_base = (uint32_t)__cvta_generic_to_shared(hsm);

    const int l4 = lane >> 2;
    const int l2 = lane & 3;
    const int bmid = lane >> 3;
    const int brow = lane & 7;
    uint32_t wsmB = (uint32_t)__cvta_generic_to_shared(
                        ((bmid < 2) ? Whi : Wlo) + (size_t)(nh*24 + brow)*WPAD)
                    + (uint32_t)((bmid & 1) * 16);

    int growx[3][2];
#pragma unroll
    for (int nt = 0; nt < 3; nt++)
#pragma unroll
        for (int jj = 0; jj < 2; jj++) {
            int row = nh*24 + nt*8 + 2*l2 + jj;
            growx[nt][jj] = (row/UPB)*HID + u0 + (row%UPB);
        }
    const int bx0 = 16*mw + l4;

    float xv[3][2][2];
    load_xv(0, bx0, growx, xv, ebih, ebhh);

    __syncthreads();

    for (int t = 0; t < 258; t++) {
        if (t >= 256) {
            const float* Wsrc = eWih + (size_t)(t - 256) * GATES * HID;
            for (int e = tid; e < RPB*HID; e += 256) {
                int rr = e / HID, k = e % HID;
                int grow = (rr/UPB)*HID + u0 + (rr%UPB);
                float w = Wsrc[(size_t)grow*HID + k];
                __half hi = __float2half(w);
                Whi[rr*WPAD + k] = hi;
                Wlo[rr*WPAD + k] = __float2half(w - __half2float(hi));
            }
            __syncthreads();
        }

        const __half* hh = g_hh[t & 1];

        // prologue: stage chunk 0 (K 0..255) into buf 0
        // granule decode: s=g&15, b=(g>>4)&63, s2=g>>10
#pragma unroll
        for (int i = 0; i < 8; i++) {
            int g = tid + i*256;
            int s = g & 15, b = (g >> 4) & 63, s2 = g >> 10;
            uint32_t dst = hs_base + (uint32_t)(s2*16384 + b*256 + ((s ^ (b&7))*16));
            const __half* src = hh + (size_t)b*HID + s2*128 + s*8;
            asm volatile("cp.async.cg.shared.global [%0], [%1], 16;" :: "r"(dst), "l"(src));
        }
        asm volatile("cp.async.commit_group;");

        float acc[3][4];
#pragma unroll
        for (int nt = 0; nt < 3; nt++)
#pragma unroll
            for (int j = 0; j < 4; j++) acc[nt][j] = 0.f;

        const int rr = lane & 15, sg = lane >> 4;
        const uint32_t rowoff = (uint32_t)((16*mw + rr)*256);
        const uint32_t swz = (uint32_t)((rr&7)*16);

        for (int rnd = 0; rnd < 3; rnd++) {
            if (rnd < 2) {
#pragma unroll
                for (int i = 0; i < 8; i++) {
                    int g = tid + i*256;
                    int s = g & 15, b = (g >> 4) & 63, s2 = g >> 10;
                    uint32_t dst = hs_base + (uint32_t)((((rnd+1)&1)*2 + s2)*16384 + b*256 + ((s ^ (b&7))*16));
                    const __half* src = hh + (size_t)b*HID + (rnd+1)*256 + s2*128 + s*8;
                    asm volatile("cp.async.cg.shared.global [%0], [%1], 16;" :: "r"(dst), "l"(src));
                }
                asm volatile("cp.async.commit_group;");
                asm volatile("cp.async.wait_group 1;");
            } else {
                asm volatile("cp.async.wait_group 0;");
            }
            __syncthreads();

            uint32_t bufb = hs_base + (uint32_t)((rnd&1)*32768);
#pragma unroll
            for (int s2 = 0; s2 < 2; s2++) {
                uint32_t subb = bufb + (uint32_t)(s2*16384);
                uint32_t kb0 = (uint32_t)((rnd*16 + s2*8)*32);
#pragma unroll
                for (int ks = 0; ks < 8; ks++) {
                    uint32_t coff = (uint32_t)(ks*32 + sg*16) ^ swz;
                    uint32_t ahi[4];
                    ldsm4(ahi, subb + rowoff + coff);
                    uint32_t kb = kb0 + (uint32_t)(ks*32);
#pragma unroll
                    for (int nt = 0; nt < 3; nt++) {
                        uint32_t bf[4];
                        ldsm4(bf, wsmB + (uint32_t)(nt*8*WPAD*2) + kb);
                        mma_f16(acc[nt], ahi, bf[0], bf[1]);
                        mma_f16(acc[nt], ahi, bf[2], bf[3]);
                    }
                }
            }
            __syncthreads();
        }

        // epilogue: full gates (no partial reduction)
#pragma unroll
        for (int nt = 0; nt < 3; nt++) {
            int r0 = nh*24 + nt*8 + 2*l2;
            gs[(r0  )*66 + bx0    ] = acc[nt][0] + xv[nt][0][0];
            gs[(r0+1)*66 + bx0    ] = acc[nt][1] + xv[nt][1][0];
            gs[(r0  )*66 + bx0 + 8] = acc[nt][2] + xv[nt][0][1];
            gs[(r0+1)*66 + bx0 + 8] = acc[nt][3] + xv[nt][1][1];
        }
        __syncthreads();

        __half* oh = g_hh[(t+1)&1];
        for (int e = tid; e < UPB*BATCH; e += 256) {
            int u = e % UPB, b = e / UPB;
            float iv = gs[(u)        *66 + b];
            float fv = gs[(UPB  + u) *66 + b];
            float gv = gs[(2*UPB+u)  *66 + b];
            float ov = gs[(3*UPB+u)  *66 + b];
            float cn, hn;
            if (t < 256) {
                float cp = c_s[e];
                cn = sigf(fv) * cp + sigf(iv) * tanhfast(gv);
                c_s[e] = cn;
            } else {
                cn = sigf(iv) * tanhfast(gv);
            }
            hn = sigf(ov) * tanhfast(cn);
            int idx = b*HID + u0 + u;
            oh[idx] = __float2half(hn);
            if (t == 255) out[OUT_ENC_OFF + idx] = hn;
            else if (t == 256) out[OUT_ENC_OFF + BATCH*HID + idx] = hn;
            else if (t == 257) out[OUT_ENC_OFF + 2*BATCH*HID + idx] = hn;
        }

        __syncthreads();
        if (tid == 0) bar_arrive(&g_bar);
        load_xv(t + 1, bx0, growx, xv, ebih, ebhh);
        if (tid == 0) {
            unsigned target = (unsigned)(t + 1) * NB;
            while (bar_poll(&g_bar) < target) {}
        }
        __syncthreads();
    }
}

// decoder path: 16 blocks, 48 units each; gate rows {i,g,o} = 144/block.
__device__ void dec_path(
    const float* __restrict__ W2, const float* __restrict__ db1,
    const float* __restrict__ db2, const float* __restrict__ linW,
    const float* __restrict__ linb, float* __restrict__ out, char* smraw)
{
    float* Ws   = (float*)smraw;            // 72*768
    float* hbuf = Ws + SROWS*HID;           // 768
    float* gs   = hbuf + HID;               // 144
    float* bs   = gs + 144;                 // 144
    float* osv  = bs + 144;                 // 16
    float* lbs  = osv + 16;                 // 16

    const int tid = threadIdx.x;
    const int blk = blockIdx.x - NB;        // 0..15
    const int u0 = blk * DUPB;
    const int f0 = blk * 16;

    for (int e = tid; e < SROWS*(HID/4); e += 256) {
        int r = e / (HID/4), c4 = e % (HID/4);
        int gi = r / DUPB;
        int grow = (gi == 0 ? 0 : 2)*HID + u0 + (r % DUPB);
        ((float4*)Ws)[e] = ((const float4*)(W2 + (size_t)grow*HID))[c4];
    }
    if (tid < 144) {
        int gi = tid / DUPB;
        int gg = (gi == 0) ? 0 : (gi == 1 ? 2 : 3);
        int grow = gg*HID + u0 + (tid % DUPB);
        bs[tid] = db1[grow] + db2[grow];
    }
    if (tid < 16) lbs[tid] = linb[f0 + tid];
    __syncthreads();

    for (int t = 0; t < TLEN; t++) {
        for (int e = tid; e < HID; e += 256) hbuf[e] = __ldcg(&g_hd[t&1][e]);
        __syncthreads();

        if (tid < 144) {
            float sum = 0.f;
            const float4* h4 = (const float4*)hbuf;
            if (tid < SROWS) {
                const float4* W4 = (const float4*)(Ws + tid*HID);
#pragma unroll 8
                for (int m = 0; m < HID/4; m++) {
                    float4 wv = W4[m]; float4 hv = h4[m];
                    sum += wv.x*hv.x + wv.y*hv.y + wv.z*hv.z + wv.w*hv.w;
                }
            } else {
                int gi = tid / DUPB;
                int gg = (gi == 1) ? 2 : 3;
                int grow = gg*HID + u0 + (tid % DUPB);
                const float4* W4 = (const float4*)(W2 + (size_t)grow*HID);
#pragma unroll 8
                for (int m = 0; m < HID/4; m++) {
                    float4 wv = __ldg(&W4[m]); float4 hv = h4[m];
                    sum += wv.x*hv.x + wv.y*hv.y + wv.z*hv.z + wv.w*hv.w;
                }
            }
            gs[tid] = sum + bs[tid];
        }
        __syncthreads();
        if (tid < DUPB) {
            float cn = sigf(gs[tid]) * tanhfast(gs[48 + tid]);
            float hn = sigf(gs[96 + tid]) * tanhfast(cn);
            __stcg(&g_hd[(t+1)&1][u0 + tid], hn);
        }
        __syncthreads();
        if (tid == 0) {
            bar_arrive(&g_bar2);
            unsigned target = (unsigned)(t + 1) * DNB;
            while (bar_poll(&g_bar2) < target) {}
        }
        __syncthreads();

        for (int e = tid; e < HID; e += 256) hbuf[e] = __ldcg(&g_hd[(t+1)&1][e]);
        __syncthreads();
        {
            int fl = tid >> 4, s = tid & 15;
            const float4* W4 = (const float4*)(linW + (size_t)(f0 + fl)*HID);
            const float4* h4 = (const float4*)hbuf;
            float p = 0.f;
#pragma unroll
            for (int m = 0; m < 12; m++) {
                float4 wv = __ldg(&W4[s + 16*m]); float4 hv = h4[s + 16*m];
                p += wv.x*hv.x + wv.y*hv.y + wv.z*hv.z + wv.w*hv.w;
            }
#pragma unroll
            for (int off = 8; off > 0; off >>= 1)
                p += __shfl_down_sync(0xffffffffu, p, off, 16);
            if (s == 0) osv[fl] = p + lbs[fl];
        }
        __syncthreads();
        for (int e = tid; e < BATCH*16; e += 256) {
            int b = e >> 4, fl = e & 15;
            out[(size_t)t*BATCH*FEAT + b*FEAT + f0 + fl] = osv[fl];
        }
        __syncthreads();
    }
}

__global__ __launch_bounds__(256) void k_encdec(
    const float* __restrict__ Whh, const float* __restrict__ eWih,
    const float* __restrict__ ebih, const float* __restrict__ ebhh,
    const float* __restrict__ W2, const float* __restrict__ db1,
    const float* __restrict__ db2, const float* __restrict__ linW,
    const float* __restrict__ linb, float* __restrict__ out)
{
    extern __shared__ char smraw[];
    if (blockIdx.x < NB)
        enc_path(Whh, eWih, ebih, ebhh, out, smraw);
    else
        dec_path(W2, db1, db2, linW, linb, out, smraw);
}

extern "C" void kernel_launch(void* const* d_in, const int* in_sizes, int n_in,
                              void* d_out, int out_size)
{
    const float* x     = (const float*)d_in[0];
    const float* Wih0  = (const float*)d_in[1];
    const float* Whh0  = (const float*)d_in[2];
    const float* bih0  = (const float*)d_in[3];
    const float* bhh0  = (const float*)d_in[4];
    const float* eWih  = (const float*)d_in[5];
    const float* ebih  = (const float*)d_in[7];
    const float* ebhh  = (const float*)d_in[8];
    const float* dWih  = (const float*)d_in[9];
    const float* dbih  = (const float*)d_in[11];
    const float* dbhh  = (const float*)d_in[12];
    const float* linW  = (const float*)d_in[13];
    const float* linb  = (const float*)d_in[14];
    float* out = (float*)d_out;

    __half *p_xh, *p_whi, *p_wlo;
    cudaGetSymbolAddress((void**)&p_xh,  g_xh);
    cudaGetSymbolAddress((void**)&p_whi, g_whi);
    cudaGetSymbolAddress((void**)&p_wlo, g_wlo);

    // enc: 148992 (W) + 65536 (h) + 12672 (gs) + 3072 (c) = 230272 B
    // dec: 225536 B
    const int fused_smem = 2*RPB*WPAD*2 + 65536 + RPB*66*4 + UPB*BATCH*4;
    const int xg_smem  = 98304 + 132*4;

    static int smem_set = 0;
    if (!smem_set) {
        cudaFuncSetAttribute(k_encdec, cudaFuncAttributeMaxDynamicSharedMemorySize, fused_smem);
        cudaFuncSetAttribute(k_xg_mma, cudaFuncAttributeMaxDynamicSharedMemorySize, xg_smem);
        smem_set = 1;
    }

    k_init<<<192, 256>>>();
    k_cvt1<<<(XM*FEAT + 511)/512, 512>>>(x, p_xh, XM*FEAT);
    k_cvt2<<<(GATES*FEAT + 511)/512, 512>>>(Wih0, p_whi, p_wlo, GATES*FEAT);
    k_xg_mma<<<dim3(24, 128), 256, xg_smem>>>(bih0, bhh0);

    k_encdec<<<NB + DNB, 256, fused_smem>>>(
        Whh0, eWih, ebih, ebhh,
        dWih + (size_t)2 * GATES * HID, dbih + 2 * GATES, dbhh + 2 * GATES,
        linW, linb, out);
}

// round 14
// speedup vs baseline: 1.2538x; 1.2538x over previous
#include <cuda_runtime.h>
#include <cuda_fp16.h>
#include <math.h>
#include <stdint.h>

#define S_LEN 256
#define BATCH 64
#define FEAT  256
#define HID   768
#define GATES 3072
#define TLEN  32
#define OUT_ENC_OFF (TLEN*BATCH*FEAT)
#define XM    (S_LEN*BATCH)

#define NB   128      // encoder blocks
#define DNB  16       // decoder blocks (fused: blockIdx 128..143)
#define DUPB 48
#define SROWS 72
#define UPB  6
#define RPB  24
#define WPAD 776

// xg stored TRANSPOSED: [t][gate_row][batch]
static __device__ float g_xg[(size_t)S_LEN*GATES*BATCH];
static __device__ __half g_xh[(size_t)XM*FEAT];
static __device__ __half g_whi[(size_t)GATES*FEAT];
static __device__ __half g_wlo[(size_t)GATES*FEAT];
static __device__ __half g_hh[2][BATCH*HID];
static __device__ float g_hd[2][HID];
static __device__ unsigned g_bar;
static __device__ unsigned g_bar2;

__device__ __forceinline__ float sigf(float x){
    return __fdividef(1.f, 1.f + __expf(-x));
}
__device__ __forceinline__ float tanhfast(float x){
    return 1.f - __fdividef(2.f, __expf(2.f*x) + 1.f);
}

__device__ __forceinline__ void mma_f16(float* c, const uint32_t* a, uint32_t b0, uint32_t b1){
    asm volatile(
        "mma.sync.aligned.m16n8k16.row.col.f32.f16.f16.f32 "
        "{%0,%1,%2,%3}, {%4,%5,%6,%7}, {%8,%9}, {%0,%1,%2,%3};"
        : "+f"(c[0]), "+f"(c[1]), "+f"(c[2]), "+f"(c[3])
        : "r"(a[0]), "r"(a[1]), "r"(a[2]), "r"(a[3]), "r"(b0), "r"(b1));
}
__device__ __forceinline__ void ldsm4(uint32_t* a, uint32_t addr){
    asm volatile("ldmatrix.sync.aligned.m8n8.x4.shared.b16 {%0,%1,%2,%3}, [%4];"
        : "=r"(a[0]), "=r"(a[1]), "=r"(a[2]), "=r"(a[3]) : "r"(addr));
}
__device__ __forceinline__ void bar_arrive(unsigned* p){
    asm volatile("red.release.gpu.global.add.u32 [%0], %1;" :: "l"(p), "r"(1u) : "memory");
}
__device__ __forceinline__ unsigned bar_poll(unsigned* p){
    unsigned v;
    asm volatile("ld.acquire.gpu.global.u32 %0, [%1];" : "=r"(v) : "l"(p) : "memory");
    return v;
}

// fused init + X conversion + W conversion (one launch)
__global__ void k_prep(const float* __restrict__ x, const float* __restrict__ Wih0) {
    int i = blockIdx.x*blockDim.x + threadIdx.x;
    if (i < BATCH*HID/2) ((uint32_t*)g_hh[0])[i] = 0u;
    if (i < HID) g_hd[0][i] = 0.f;
    if (i == 0) { g_bar = 0u; g_bar2 = 0u; }
    if (i < XM*FEAT) g_xh[i] = __float2half(x[i]);
    if (i < GATES*FEAT) {
        float v = Wih0[i];
        __half hi = __float2half(v);
        g_whi[i] = hi;
        g_wlo[i] = __float2half(v - __half2float(hi));
    }
}

// ---------------- tensor-core xg GEMM (single-buffer, ldsm-B) -------------
__global__ __launch_bounds__(256, 2) void k_xg_mma(
    const float* __restrict__ b1, const float* __restrict__ b2)
{
    extern __shared__ char smraw[];
    uint32_t xs_base = (uint32_t)__cvta_generic_to_shared(smraw);
    uint32_t ws_base = xs_base + 32768;
    float* sbias = (float*)(smraw + 98304);

    const int tid  = threadIdx.x;
    const int wid  = tid >> 5;
    const int lane = tid & 31;
    const int mw   = wid & 3;
    const int nw   = wid >> 2;
    const int bn   = blockIdx.x * 128;
    const int bm   = blockIdx.y * 128;
    const int l4 = lane >> 2;
    const int l2 = lane & 3;
    const int r  = lane & 15;
    const int seg = lane >> 4;
    const int bmid = lane >> 3;
    const int brow = lane & 7;

    if (tid < 128) sbias[tid] = b1[bn+tid] + b2[bn+tid];

    float acc[2][8][4];
#pragma unroll
    for (int mt = 0; mt < 2; mt++)
#pragma unroll
        for (int nt = 0; nt < 8; nt++)
#pragma unroll
            for (int j = 0; j < 4; j++) acc[mt][nt][j] = 0.f;

    for (int ph = 0; ph < 2; ph++) {
        __syncthreads();
#pragma unroll
        for (int i = 0; i < 8; i++) {
            int g = tid + i*256;
            int s = g & 15, row = g >> 4;
            uint32_t dst = xs_base + (uint32_t)(row*256 + ((s ^ (row&7))*16));
            const __half* src = g_xh + (size_t)(bm+row)*FEAT + ph*128 + s*8;
            asm volatile("cp.async.cg.shared.global [%0], [%1], 16;" :: "r"(dst), "l"(src));
        }
#pragma unroll
        for (int i = 0; i < 16; i++) {
            int g = tid + i*256;
            int s = g & 15, row = (g >> 4) & 127, pl = g >> 11;
            uint32_t dst = ws_base + (uint32_t)(pl*32768 + row*256 + ((s ^ (row&7))*16));
            const __half* src = (pl ? g_wlo : g_whi) + (size_t)(bn+row)*FEAT + ph*128 + s*8;
            asm volatile("cp.async.cg.shared.global [%0], [%1], 16;" :: "r"(dst), "l"(src));
        }
        asm volatile("cp.async.commit_group;");
        asm volatile("cp.async.wait_group 0;");
        __syncthreads();

#pragma unroll
        for (int ks = 0; ks < 8; ks++) {
            uint32_t ahi[2][4];
#pragma unroll
            for (int mt = 0; mt < 2; mt++) {
                uint32_t rowoff = (uint32_t)((mw*32 + mt*16 + r)*256);
                uint32_t coff = (uint32_t)((ks*32 + seg*16) ^ ((r&7)*16));
                ldsm4(ahi[mt], xs_base + rowoff + coff);
            }
#pragma unroll
            for (int nt = 0; nt < 8; nt++) {
                int wrow = nw*64 + nt*8 + brow;
                uint32_t baddr = ws_base + (uint32_t)((bmid>>1)*32768 + wrow*256
                                 + (((ks*2 + (bmid&1)) ^ brow)*16));
                uint32_t bf[4];
                ldsm4(bf, baddr);
#pragma unroll
                for (int mt = 0; mt < 2; mt++) {
                    mma_f16(acc[mt][nt], ahi[mt], bf[0], bf[1]);
                    mma_f16(acc[mt][nt], ahi[mt], bf[2], bf[3]);
                }
            }
        }
    }

#pragma unroll
    for (int mt = 0; mt < 2; mt++) {
#pragma unroll
        for (int nt = 0; nt < 8; nt++) {
            int nloc = nw*64 + nt*8 + 2*l2;
            int n0 = bn + nloc;
            int m0 = bm + mw*32 + mt*16 + l4;
            int t = m0 >> 6, b = m0 & 63;
            size_t base = (size_t)t*GATES*BATCH;
            float bi0 = sbias[nloc], bi1 = sbias[nloc+1];
            g_xg[base + (size_t)n0*BATCH + b]         = acc[mt][nt][0] + bi0;
            g_xg[base + (size_t)(n0+1)*BATCH + b]     = acc[mt][nt][1] + bi1;
            g_xg[base + (size_t)n0*BATCH + b + 8]     = acc[mt][nt][2] + bi0;
            g_xg[base + (size_t)(n0+1)*BATCH + b + 8] = acc[mt][nt][3] + bi1;
        }
    }
}

// ---------------- fused persistent kernel: encoder (blocks 0..127) +
//                  decoder (blocks 128..143, independent, overlapped) ------
__device__ __forceinline__ void load_xv(int t, int kh, int bx0,
                                        const int growx[3][2], float xv[3][2][2],
                                        const float* __restrict__ eb1,
                                        const float* __restrict__ eb2)
{
    if (kh != 0 || t >= 258) return;
    if (t < 256) {
        const float* xg = g_xg + (size_t)t * GATES * BATCH;
#pragma unroll
        for (int nt = 0; nt < 3; nt++)
#pragma unroll
            for (int jj = 0; jj < 2; jj++) {
                const float* rowp = xg + (size_t)growx[nt][jj]*BATCH + bx0;
                xv[nt][jj][0] = __ldcg(rowp);
                xv[nt][jj][1] = __ldcg(rowp + 8);
            }
    } else {
        int l = t - 256;
#pragma unroll
        for (int nt = 0; nt < 3; nt++)
#pragma unroll
            for (int jj = 0; jj < 2; jj++) {
                float bb = __ldg(eb1 + l*GATES + growx[nt][jj]) +
                           __ldg(eb2 + l*GATES + growx[nt][jj]);
                xv[nt][jj][0] = bb;
                xv[nt][jj][1] = bb;
            }
    }
}

__device__ void enc_path(
    const float* __restrict__ Whh, const float* __restrict__ eWih,
    const float* __restrict__ ebih, const float* __restrict__ ebhh,
    float* __restrict__ out, char* smraw)
{
    __half* Whi = (__half*)smraw;
    __half* Wlo = Whi + RPB*WPAD;
    __half* hsm = Wlo + RPB*WPAD;
    float* gA  = (float*)((char*)hsm + 98304);
    float* gB  = gA + RPB*66;
    float* c_s = gB + RPB*66;

    const int tid  = threadIdx.x;
    const int wid  = tid >> 5;
    const int lane = tid & 31;
    const int mw   = wid & 3;
    const int kh   = wid >> 2;
    const int u0   = blockIdx.x * UPB;

    for (int e = tid; e < RPB*HID; e += 256) {
        int rr = e / HID, k = e % HID;
        int grow = (rr/UPB)*HID + u0 + (rr%UPB);
        float w = Whh[(size_t)grow*HID + k];
        __half hi = __float2half(w);
        Whi[rr*WPAD + k] = hi;
        Wlo[rr*WPAD + k] = __float2half(w - __half2float(hi));
    }
    for (int e = tid; e < UPB*BATCH; e += 256) c_s[e] = 0.f;

    uint32_t hs_base = (uint32_t)__cvta_generic_to_shared(hsm);

    const int l4 = lane >> 2;
    const int l2 = lane & 3;
    const int bmid = lane >> 3;
    const int brow = lane & 7;
    uint32_t wsmB = (uint32_t)__cvta_generic_to_shared(
                        ((bmid < 2) ? Whi : Wlo) + (size_t)brow*WPAD)
                    + (uint32_t)((bmid & 1) * 16);

    int growx[3][2];
#pragma unroll
    for (int nt = 0; nt < 3; nt++)
#pragma unroll
        for (int jj = 0; jj < 2; jj++) {
            int row = nt*8 + 2*l2 + jj;
            growx[nt][jj] = (row/UPB)*HID + u0 + (row%UPB);
        }
    const int bx0 = 16*mw + l4;

    float xv[3][2][2];
    load_xv(0, kh, bx0, growx, xv, ebih, ebhh);

    __syncthreads();

    for (int t = 0; t < 258; t++) {
        if (t >= 256) {
            const float* Wsrc = eWih + (size_t)(t - 256) * GATES * HID;
            for (int e = tid; e < RPB*HID; e += 256) {
                int rr = e / HID, k = e % HID;
                int grow = (rr/UPB)*HID + u0 + (rr%UPB);
                float w = Wsrc[(size_t)grow*HID + k];
                __half hi = __float2half(w);
                Whi[rr*WPAD + k] = hi;
                Wlo[rr*WPAD + k] = __float2half(w - __half2float(hi));
            }
            __syncthreads();
        }

        const __half* hh = g_hh[t & 1];

#pragma unroll
        for (int i = 0; i < 24; i++) {
            int g = tid + i*256;
            int s = g & 15, b = (g >> 4) & 63, c = g >> 10;
            uint32_t dst = hs_base + (uint32_t)(c*16384 + b*256 + ((s ^ (b&7))*16));
            const __half* src = hh + (size_t)b*HID + c*128 + s*8;
            asm volatile("cp.async.cg.shared.global [%0], [%1], 16;" :: "r"(dst), "l"(src));
        }
        asm volatile("cp.async.commit_group;");
        asm volatile("cp.async.wait_group 0;");
        __syncthreads();

        float acc[3][4];
#pragma unroll
        for (int nt = 0; nt < 3; nt++)
#pragma unroll
            for (int j = 0; j < 4; j++) acc[nt][j] = 0.f;

        const int rr = lane & 15, sg = lane >> 4;
        const uint32_t rowoff = (uint32_t)((16*mw + rr)*256);
        const uint32_t swz = (uint32_t)((rr&7)*16);
#pragma unroll
        for (int p = 0; p < 3; p++) {
            const int c = 3*kh + p;
            uint32_t subb = hs_base + (uint32_t)(c*16384);
            uint32_t kbyte0 = (uint32_t)(c*256);
#pragma unroll
            for (int ks = 0; ks < 8; ks++) {
                uint32_t coff = (uint32_t)(ks*32 + sg*16) ^ swz;
                uint32_t ahi[4];
                ldsm4(ahi, subb + rowoff + coff);
                uint32_t kb = kbyte0 + (uint32_t)(ks*32);
#pragma unroll
                for (int nt = 0; nt < 3; nt++) {
                    uint32_t bf[4];
                    ldsm4(bf, wsmB + (uint32_t)(nt*8*WPAD*2) + kb);
                    mma_f16(acc[nt], ahi, bf[0], bf[1]);
                    mma_f16(acc[nt], ahi, bf[2], bf[3]);
                }
            }
        }

        float* dst = kh ? gB : gA;
#pragma unroll
        for (int nt = 0; nt < 3; nt++) {
            int r0 = nt*8 + 2*l2;
            if (kh == 0) {
                dst[(r0  )*66 + bx0    ] = acc[nt][0] + xv[nt][0][0];
                dst[(r0+1)*66 + bx0    ] = acc[nt][1] + xv[nt][1][0];
                dst[(r0  )*66 + bx0 + 8] = acc[nt][2] + xv[nt][0][1];
                dst[(r0+1)*66 + bx0 + 8] = acc[nt][3] + xv[nt][1][1];
            } else {
                dst[(r0  )*66 + bx0    ] = acc[nt][0];
                dst[(r0+1)*66 + bx0    ] = acc[nt][1];
                dst[(r0  )*66 + bx0 + 8] = acc[nt][2];
                dst[(r0+1)*66 + bx0 + 8] = acc[nt][3];
            }
        }
        __syncthreads();

        __half* oh = g_hh[(t+1)&1];
        for (int e = tid; e < UPB*BATCH; e += 256) {
            int u = e % UPB, b = e / UPB;
            float iv = gA[(u)       *66 + b] + gB[(u)       *66 + b];
            float fv = gA[(UPB  +u) *66 + b] + gB[(UPB  +u) *66 + b];
            float gv = gA[(2*UPB+u) *66 + b] + gB[(2*UPB+u) *66 + b];
            float ov = gA[(3*UPB+u) *66 + b] + gB[(3*UPB+u) *66 + b];
            float cn, hn;
            if (t < 256) {
                float cp = c_s[e];
                cn = sigf(fv) * cp + sigf(iv) * tanhfast(gv);
                c_s[e] = cn;
            } else {
                cn = sigf(iv) * tanhfast(gv);
            }
            hn = sigf(ov) * tanhfast(cn);
            int idx = b*HID + u0 + u;
            oh[idx] = __float2half(hn);
            if (t == 255) out[OUT_ENC_OFF + idx] = hn;
            else if (t == 256) out[OUT_ENC_OFF + BATCH*HID + idx] = hn;
            else if (t == 257) out[OUT_ENC_OFF + 2*BATCH*HID + idx] = hn;
        }

        __syncthreads();
        if (tid == 0) bar_arrive(&g_bar);
        load_xv(t + 1, kh, bx0, growx, xv, ebih, ebhh);
        if (tid == 0) {
            unsigned target = (unsigned)(t + 1) * NB;
            while (bar_poll(&g_bar) < target) {}
        }
        __syncthreads();
    }
}

// decoder path: 16 blocks, 48 units each; gate rows {i,g,o} = 144/block.
__device__ void dec_path(
    const float* __restrict__ W2, const float* __restrict__ db1,
    const float* __restrict__ db2, const float* __restrict__ linW,
    const float* __restrict__ linb, float* __restrict__ out, char* smraw)
{
    float* Ws   = (float*)smraw;
    float* hbuf = Ws + SROWS*HID;
    float* gs   = hbuf + HID;
    float* bs   = gs + 144;
    float* osv  = bs + 144;
    float* lbs  = osv + 16;

    const int tid = threadIdx.x;
    const int blk = blockIdx.x - NB;
    const int u0 = blk * DUPB;
    const int f0 = blk * 16;

    for (int e = tid; e < SROWS*(HID/4); e += 256) {
        int r = e / (HID/4), c4 = e % (HID/4);
        int gi = r / DUPB;
        int grow = (gi == 0 ? 0 : 2)*HID + u0 + (r % DUPB);
        ((float4*)Ws)[e] = ((const float4*)(W2 + (size_t)grow*HID))[c4];
    }
    if (tid < 144) {
        int gi = tid / DUPB;
        int gg = (gi == 0) ? 0 : (gi == 1 ? 2 : 3);
        int grow = gg*HID + u0 + (tid % DUPB);
        bs[tid] = db1[grow] + db2[grow];
    }
    if (tid < 16) lbs[tid] = linb[f0 + tid];
    __syncthreads();

    for (int t = 0; t < TLEN; t++) {
        for (int e = tid; e < HID; e += 256) hbuf[e] = __ldcg(&g_hd[t&1][e]);
        __syncthreads();

        if (tid < 144) {
            float sum = 0.f;
            const float4* h4 = (const float4*)hbuf;
            if (tid < SROWS) {
                const float4* W4 = (const float4*)(Ws + tid*HID);
#pragma unroll 8
                for (int m = 0; m < HID/4; m++) {
                    float4 wv = W4[m]; float4 hv = h4[m];
                    sum += wv.x*hv.x + wv.y*hv.y + wv.z*hv.z + wv.w*hv.w;
                }
            } else {
                int gi = tid / DUPB;
                int gg = (gi == 1) ? 2 : 3;
                int grow = gg*HID + u0 + (tid % DUPB);
                const float4* W4 = (const float4*)(W2 + (size_t)grow*HID);
#pragma unroll 8
                for (int m = 0; m < HID/4; m++) {
                    float4 wv = __ldg(&W4[m]); float4 hv = h4[m];
                    sum += wv.x*hv.x + wv.y*hv.y + wv.z*hv.z + wv.w*hv.w;
                }
            }
            gs[tid] = sum + bs[tid];
        }
        __syncthreads();
        if (tid < DUPB) {
            float cn = sigf(gs[tid]) * tanhfast(gs[48 + tid]);
            float hn = sigf(gs[96 + tid]) * tanhfast(cn);
            __stcg(&g_hd[(t+1)&1][u0 + tid], hn);
        }
        __syncthreads();
        if (tid == 0) {
            bar_arrive(&g_bar2);
            unsigned target = (unsigned)(t + 1) * DNB;
            while (bar_poll(&g_bar2) < target) {}
        }
        __syncthreads();

        for (int e = tid; e < HID; e += 256) hbuf[e] = __ldcg(&g_hd[(t+1)&1][e]);
        __syncthreads();
        {
            int fl = tid >> 4, s = tid & 15;
            const float4* W4 = (const float4*)(linW + (size_t)(f0 + fl)*HID);
            const float4* h4 = (const float4*)hbuf;
            float p = 0.f;
#pragma unroll
            for (int m = 0; m < 12; m++) {
                float4 wv = __ldg(&W4[s + 16*m]); float4 hv = h4[s + 16*m];
                p += wv.x*hv.x + wv.y*hv.y + wv.z*hv.z + wv.w*hv.w;
            }
#pragma unroll
            for (int off = 8; off > 0; off >>= 1)
                p += __shfl_down_sync(0xffffffffu, p, off, 16);
            if (s == 0) osv[fl] = p + lbs[fl];
        }
        __syncthreads();
        for (int e = tid; e < BATCH*16; e += 256) {
            int b = e >> 4, fl = e & 15;
            out[(size_t)t*BATCH*FEAT + b*FEAT + f0 + fl] = osv[fl];
        }
        __syncthreads();
    }
}

__global__ __launch_bounds__(256) void k_encdec(
    const float* __restrict__ Whh, const float* __restrict__ eWih,
    const float* __restrict__ ebih, const float* __restrict__ ebhh,
    const float* __restrict__ W2, const float* __restrict__ db1,
    const float* __restrict__ db2, const float* __restrict__ linW,
    const float* __restrict__ linb, float* __restrict__ out)
{
    extern __shared__ char smraw[];
    if (blockIdx.x < NB)
        enc_path(Whh, eWih, ebih, ebhh, out, smraw);
    else
        dec_path(W2, db1, db2, linW, linb, out, smraw);
}

extern "C" void kernel_launch(void* const* d_in, const int* in_sizes, int n_in,
                              void* d_out, int out_size)
{
    const float* x     = (const float*)d_in[0];
    const float* Wih0  = (const float*)d_in[1];
    const float* Whh0  = (const float*)d_in[2];
    const float* bih0  = (const float*)d_in[3];
    const float* bhh0  = (const float*)d_in[4];
    const float* eWih  = (const float*)d_in[5];
    const float* ebih  = (const float*)d_in[7];
    const float* ebhh  = (const float*)d_in[8];
    const float* dWih  = (const float*)d_in[9];
    const float* dbih  = (const float*)d_in[11];
    const float* dbhh  = (const float*)d_in[12];
    const float* linW  = (const float*)d_in[13];
    const float* linb  = (const float*)d_in[14];
    float* out = (float*)d_out;

    // enc layout 187008 B; dec layout 225536 B -> request max
    const int fused_smem = (SROWS*HID + HID + 144 + 144 + 16 + 16) * 4;
    const int xg_smem  = 98304 + 132*4;

    static int smem_set = 0;
    if (!smem_set) {
        cudaFuncSetAttribute(k_encdec, cudaFuncAttributeMaxDynamicSharedMemorySize, fused_smem);
        cudaFuncSetAttribute(k_xg_mma, cudaFuncAttributeMaxDynamicSharedMemorySize, xg_smem);
        smem_set = 1;
    }

    k_prep<<<(XM*FEAT + 511)/512, 512>>>(x, Wih0);
    k_xg_mma<<<dim3(24, 128), 256, xg_smem>>>(bih0, bhh0);

    k_encdec<<<NB + DNB, 256, fused_smem>>>(
        Whh0, eWih, ebih, ebhh,
        dWih + (size_t)2 * GATES * HID, dbih + 2 * GATES, dbhh + 2 * GATES,
        linW, linb, out);
}

// round 15
// speedup vs baseline: 1.5623x; 1.2460x over previous
#include <cuda_runtime.h>
#include <cuda_fp16.h>
#include <math.h>
#include <stdint.h>

#define S_LEN 256
#define BATCH 64
#define FEAT  256
#define HID   768
#define GATES 3072
#define TLEN  32
#define OUT_ENC_OFF (TLEN*BATCH*FEAT)
#define XM    (S_LEN*BATCH)

#define NB   128      // encoder blocks
#define DNB  16       // decoder blocks (fused: blockIdx 128..143)
#define DUPB 48
#define SROWS 72
#define UPB  6
#define RPB  24
#define WPAD 776

// xg stored TRANSPOSED: [t][gate_row][batch]
static __device__ float g_xg[(size_t)S_LEN*GATES*BATCH];
static __device__ __half g_xh[(size_t)XM*FEAT];
static __device__ __half g_whi[(size_t)GATES*FEAT];
static __device__ __half g_hh[2][BATCH*HID];
static __device__ float g_hd[2][HID];
static __device__ unsigned g_bar;
static __device__ unsigned g_bar2;

__device__ __forceinline__ float sigf(float x){
    return __fdividef(1.f, 1.f + __expf(-x));
}
__device__ __forceinline__ float tanhfast(float x){
    return 1.f - __fdividef(2.f, __expf(2.f*x) + 1.f);
}

__device__ __forceinline__ void mma_f16(float* c, const uint32_t* a, uint32_t b0, uint32_t b1){
    asm volatile(
        "mma.sync.aligned.m16n8k16.row.col.f32.f16.f16.f32 "
        "{%0,%1,%2,%3}, {%4,%5,%6,%7}, {%8,%9}, {%0,%1,%2,%3};"
        : "+f"(c[0]), "+f"(c[1]), "+f"(c[2]), "+f"(c[3])
        : "r"(a[0]), "r"(a[1]), "r"(a[2]), "r"(a[3]), "r"(b0), "r"(b1));
}
__device__ __forceinline__ void ldsm4(uint32_t* a, uint32_t addr){
    asm volatile("ldmatrix.sync.aligned.m8n8.x4.shared.b16 {%0,%1,%2,%3}, [%4];"
        : "=r"(a[0]), "=r"(a[1]), "=r"(a[2]), "=r"(a[3]) : "r"(addr));
}
__device__ __forceinline__ void bar_arrive(unsigned* p){
    asm volatile("red.release.gpu.global.add.u32 [%0], %1;" :: "l"(p), "r"(1u) : "memory");
}
__device__ __forceinline__ unsigned bar_poll(unsigned* p){
    unsigned v;
    asm volatile("ld.acquire.gpu.global.u32 %0, [%1];" : "=r"(v) : "l"(p) : "memory");
    return v;
}

// fused init + X conversion + W conversion (one launch, fp16 hi-only)
__global__ void k_prep(const float* __restrict__ x, const float* __restrict__ Wih0) {
    int i = blockIdx.x*blockDim.x + threadIdx.x;
    if (i < BATCH*HID/2) ((uint32_t*)g_hh[0])[i] = 0u;
    if (i < HID) g_hd[0][i] = 0.f;
    if (i == 0) { g_bar = 0u; g_bar2 = 0u; }
    if (i < XM*FEAT) g_xh[i] = __float2half(x[i]);
    if (i < GATES*FEAT) g_whi[i] = __float2half(Wih0[i]);
}

// ---------------- tensor-core xg GEMM (fp16 hi-only, ldsm-B 4-matrix) -----
__global__ __launch_bounds__(256, 3) void k_xg_mma(
    const float* __restrict__ b1, const float* __restrict__ b2)
{
    extern __shared__ char smraw[];
    uint32_t xs_base = (uint32_t)__cvta_generic_to_shared(smraw);     // 32KB
    uint32_t ws_base = xs_base + 32768;                               // 32KB (hi only)
    float* sbias = (float*)(smraw + 65536);

    const int tid  = threadIdx.x;
    const int wid  = tid >> 5;
    const int lane = tid & 31;
    const int mw   = wid & 3;
    const int nw   = wid >> 2;
    const int bn   = blockIdx.x * 128;
    const int bm   = blockIdx.y * 128;
    const int l4 = lane >> 2;
    const int l2 = lane & 3;
    const int r  = lane & 15;
    const int seg = lane >> 4;
    const int bmid = lane >> 3;
    const int brow = lane & 7;

    if (tid < 128) sbias[tid] = b1[bn+tid] + b2[bn+tid];

    float acc[2][8][4];
#pragma unroll
    for (int mt = 0; mt < 2; mt++)
#pragma unroll
        for (int nt = 0; nt < 8; nt++)
#pragma unroll
            for (int j = 0; j < 4; j++) acc[mt][nt][j] = 0.f;

    for (int ph = 0; ph < 2; ph++) {
        __syncthreads();
        // X: 2048 granules (8/thread)
#pragma unroll
        for (int i = 0; i < 8; i++) {
            int g = tid + i*256;
            int s = g & 15, row = g >> 4;
            uint32_t dst = xs_base + (uint32_t)(row*256 + ((s ^ (row&7))*16));
            const __half* src = g_xh + (size_t)(bm+row)*FEAT + ph*128 + s*8;
            asm volatile("cp.async.cg.shared.global [%0], [%1], 16;" :: "r"(dst), "l"(src));
        }
        // W hi: 2048 granules (8/thread)
#pragma unroll
        for (int i = 0; i < 8; i++) {
            int g = tid + i*256;
            int s = g & 15, row = g >> 4;
            uint32_t dst = ws_base + (uint32_t)(row*256 + ((s ^ (row&7))*16));
            const __half* src = g_whi + (size_t)(bn+row)*FEAT + ph*128 + s*8;
            asm volatile("cp.async.cg.shared.global [%0], [%1], 16;" :: "r"(dst), "l"(src));
        }
        asm volatile("cp.async.commit_group;");
        asm volatile("cp.async.wait_group 0;");
        __syncthreads();

#pragma unroll
        for (int ks2 = 0; ks2 < 4; ks2++) {
            uint32_t ahi[2][2][4];
#pragma unroll
            for (int mt = 0; mt < 2; mt++) {
                uint32_t rowoff = (uint32_t)((mw*32 + mt*16 + r)*256);
#pragma unroll
                for (int j = 0; j < 2; j++) {
                    uint32_t coff = (uint32_t)(((ks2*2 + j)*32 + seg*16) ^ ((r&7)*16));
                    ldsm4(ahi[mt][j], xs_base + rowoff + coff);
                }
            }
#pragma unroll
            for (int nt = 0; nt < 8; nt++) {
                // one ldsm4: matrices {k, k+8, k+16, k+24} for this nt
                int wrow = nw*64 + nt*8 + brow;
                uint32_t baddr = ws_base + (uint32_t)(wrow*256
                                 + (((ks2*4 + bmid) ^ brow)*16));
                uint32_t bf[4];
                ldsm4(bf, baddr);
#pragma unroll
                for (int mt = 0; mt < 2; mt++) {
                    mma_f16(acc[mt][nt], ahi[mt][0], bf[0], bf[1]);
                    mma_f16(acc[mt][nt], ahi[mt][1], bf[2], bf[3]);
                }
            }
        }
    }

#pragma unroll
    for (int mt = 0; mt < 2; mt++) {
#pragma unroll
        for (int nt = 0; nt < 8; nt++) {
            int nloc = nw*64 + nt*8 + 2*l2;
            int n0 = bn + nloc;
            int m0 = bm + mw*32 + mt*16 + l4;
            int t = m0 >> 6, b = m0 & 63;
            size_t base = (size_t)t*GATES*BATCH;
            float bi0 = sbias[nloc], bi1 = sbias[nloc+1];
            g_xg[base + (size_t)n0*BATCH + b]         = acc[mt][nt][0] + bi0;
            g_xg[base + (size_t)(n0+1)*BATCH + b]     = acc[mt][nt][1] + bi1;
            g_xg[base + (size_t)n0*BATCH + b + 8]     = acc[mt][nt][2] + bi0;
            g_xg[base + (size_t)(n0+1)*BATCH + b + 8] = acc[mt][nt][3] + bi1;
        }
    }
}

// ---------------- fused persistent kernel: encoder (blocks 0..127) +
//                  decoder (blocks 128..143, independent, overlapped) ------
__device__ __forceinline__ void load_xv(int t, int kh, int bx0,
                                        const int growx[3][2], float xv[3][2][2],
                                        const float* __restrict__ eb1,
                                        const float* __restrict__ eb2)
{
    if (kh != 0 || t >= 258) return;
    if (t < 256) {
        const float* xg = g_xg + (size_t)t * GATES * BATCH;
#pragma unroll
        for (int nt = 0; nt < 3; nt++)
#pragma unroll
            for (int jj = 0; jj < 2; jj++) {
                const float* rowp = xg + (size_t)growx[nt][jj]*BATCH + bx0;
                xv[nt][jj][0] = __ldcg(rowp);
                xv[nt][jj][1] = __ldcg(rowp + 8);
            }
    } else {
        int l = t - 256;
#pragma unroll
        for (int nt = 0; nt < 3; nt++)
#pragma unroll
            for (int jj = 0; jj < 2; jj++) {
                float bb = __ldg(eb1 + l*GATES + growx[nt][jj]) +
                           __ldg(eb2 + l*GATES + growx[nt][jj]);
                xv[nt][jj][0] = bb;
                xv[nt][jj][1] = bb;
            }
    }
}

__device__ void enc_path(
    const float* __restrict__ Whh, const float* __restrict__ eWih,
    const float* __restrict__ ebih, const float* __restrict__ ebhh,
    float* __restrict__ out, char* smraw)
{
    __half* Whi = (__half*)smraw;                      // 24*776 (hi only)
    __half* hsm = Whi + RPB*WPAD;                      // 6 subtiles * 16KB
    float* gA  = (float*)((char*)hsm + 98304);
    float* gB  = gA + RPB*66;
    float* c_s = gB + RPB*66;

    const int tid  = threadIdx.x;
    const int wid  = tid >> 5;
    const int lane = tid & 31;
    const int mw   = wid & 3;
    const int kh   = wid >> 2;
    const int u0   = blockIdx.x * UPB;

    for (int e = tid; e < RPB*HID; e += 256) {
        int rr = e / HID, k = e % HID;
        int grow = (rr/UPB)*HID + u0 + (rr%UPB);
        Whi[rr*WPAD + k] = __float2half(Whh[(size_t)grow*HID + k]);
    }
    for (int e = tid; e < UPB*BATCH; e += 256) c_s[e] = 0.f;

    uint32_t hs_base = (uint32_t)__cvta_generic_to_shared(hsm);

    const int l4 = lane >> 2;
    const int l2 = lane & 3;
    const int bmid = lane >> 3;
    const int brow = lane & 7;
    // B ldsm base: row brow (within nt tile), matrix bmid -> col byte +16*bmid
    uint32_t wsmB = (uint32_t)__cvta_generic_to_shared(Whi + (size_t)brow*WPAD)
                    + (uint32_t)(bmid * 16);

    int growx[3][2];
#pragma unroll
    for (int nt = 0; nt < 3; nt++)
#pragma unroll
        for (int jj = 0; jj < 2; jj++) {
            int row = nt*8 + 2*l2 + jj;
            growx[nt][jj] = (row/UPB)*HID + u0 + (row%UPB);
        }
    const int bx0 = 16*mw + l4;

    float xv[3][2][2];
    load_xv(0, kh, bx0, growx, xv, ebih, ebhh);

    __syncthreads();

    for (int t = 0; t < 258; t++) {
        if (t >= 256) {
            const float* Wsrc = eWih + (size_t)(t - 256) * GATES * HID;
            for (int e = tid; e < RPB*HID; e += 256) {
                int rr = e / HID, k = e % HID;
                int grow = (rr/UPB)*HID + u0 + (rr%UPB);
                Whi[rr*WPAD + k] = __float2half(Wsrc[(size_t)grow*HID + k]);
            }
            __syncthreads();
        }

        const __half* hh = g_hh[t & 1];

        // stage full h (96KB) in one volley
#pragma unroll
        for (int i = 0; i < 24; i++) {
            int g = tid + i*256;
            int s = g & 15, b = (g >> 4) & 63, c = g >> 10;
            uint32_t dst = hs_base + (uint32_t)(c*16384 + b*256 + ((s ^ (b&7))*16));
            const __half* src = hh + (size_t)b*HID + c*128 + s*8;
            asm volatile("cp.async.cg.shared.global [%0], [%1], 16;" :: "r"(dst), "l"(src));
        }
        asm volatile("cp.async.commit_group;");
        asm volatile("cp.async.wait_group 0;");
        __syncthreads();

        float acc[3][4];
#pragma unroll
        for (int nt = 0; nt < 3; nt++)
#pragma unroll
            for (int j = 0; j < 4; j++) acc[nt][j] = 0.f;

        const int rr = lane & 15, sg = lane >> 4;
        const uint32_t rowoff = (uint32_t)((16*mw + rr)*256);
        const uint32_t swz = (uint32_t)((rr&7)*16);
#pragma unroll
        for (int p = 0; p < 3; p++) {
            const int c = 3*kh + p;
            uint32_t subb = hs_base + (uint32_t)(c*16384);
            uint32_t kbyte0 = (uint32_t)(c*256);
#pragma unroll
            for (int ks2 = 0; ks2 < 4; ks2++) {
                uint32_t a0[4], a1[4];
                uint32_t coff0 = (uint32_t)((ks2*2  )*32 + sg*16) ^ swz;
                uint32_t coff1 = (uint32_t)((ks2*2+1)*32 + sg*16) ^ swz;
                ldsm4(a0, subb + rowoff + coff0);
                ldsm4(a1, subb + rowoff + coff1);
                uint32_t kb = kbyte0 + (uint32_t)(ks2*64);
#pragma unroll
                for (int nt = 0; nt < 3; nt++) {
                    uint32_t bf[4];
                    ldsm4(bf, wsmB + (uint32_t)(nt*8*WPAD*2) + kb);
                    mma_f16(acc[nt], a0, bf[0], bf[1]);
                    mma_f16(acc[nt], a1, bf[2], bf[3]);
                }
            }
        }

        float* dst = kh ? gB : gA;
#pragma unroll
        for (int nt = 0; nt < 3; nt++) {
            int r0 = nt*8 + 2*l2;
            if (kh == 0) {
                dst[(r0  )*66 + bx0    ] = acc[nt][0] + xv[nt][0][0];
                dst[(r0+1)*66 + bx0    ] = acc[nt][1] + xv[nt][1][0];
                dst[(r0  )*66 + bx0 + 8] = acc[nt][2] + xv[nt][0][1];
                dst[(r0+1)*66 + bx0 + 8] = acc[nt][3] + xv[nt][1][1];
            } else {
                dst[(r0  )*66 + bx0    ] = acc[nt][0];
                dst[(r0+1)*66 + bx0    ] = acc[nt][1];
                dst[(r0  )*66 + bx0 + 8] = acc[nt][2];
                dst[(r0+1)*66 + bx0 + 8] = acc[nt][3];
            }
        }
        __syncthreads();

        __half* oh = g_hh[(t+1)&1];
        for (int e = tid; e < UPB*BATCH; e += 256) {
            int u = e % UPB, b = e / UPB;
            float iv = gA[(u)       *66 + b] + gB[(u)       *66 + b];
            float fv = gA[(UPB  +u) *66 + b] + gB[(UPB  +u) *66 + b];
            float gv = gA[(2*UPB+u) *66 + b] + gB[(2*UPB+u) *66 + b];
            float ov = gA[(3*UPB+u) *66 + b] + gB[(3*UPB+u) *66 + b];
            float cn, hn;
            if (t < 256) {
                float cp = c_s[e];
                cn = sigf(fv) * cp + sigf(iv) * tanhfast(gv);
                c_s[e] = cn;
            } else {
                cn = sigf(iv) * tanhfast(gv);
            }
            hn = sigf(ov) * tanhfast(cn);
            int idx = b*HID + u0 + u;
            oh[idx] = __float2half(hn);
            if (t == 255) out[OUT_ENC_OFF + idx] = hn;
            else if (t == 256) out[OUT_ENC_OFF + BATCH*HID + idx] = hn;
            else if (t == 257) out[OUT_ENC_OFF + 2*BATCH*HID + idx] = hn;
        }

        __syncthreads();
        if (tid == 0) bar_arrive(&g_bar);
        load_xv(t + 1, kh, bx0, growx, xv, ebih, ebhh);
        if (tid == 0) {
            unsigned target = (unsigned)(t + 1) * NB;
            while (bar_poll(&g_bar) < target) {}
        }
        __syncthreads();
    }
}

// decoder path: 16 blocks, 48 units each; gate rows {i,g,o} = 144/block.
__device__ void dec_path(
    const float* __restrict__ W2, const float* __restrict__ db1,
    const float* __restrict__ db2, const float* __restrict__ linW,
    const float* __restrict__ linb, float* __restrict__ out, char* smraw)
{
    float* Ws   = (float*)smraw;
    float* hbuf = Ws + SROWS*HID;
    float* gs   = hbuf + HID;
    float* bs   = gs + 144;
    float* osv  = bs + 144;
    float* lbs  = osv + 16;

    const int tid = threadIdx.x;
    const int blk = blockIdx.x - NB;
    const int u0 = blk * DUPB;
    const int f0 = blk * 16;

    for (int e = tid; e < SROWS*(HID/4); e += 256) {
        int r = e / (HID/4), c4 = e % (HID/4);
        int gi = r / DUPB;
        int grow = (gi == 0 ? 0 : 2)*HID + u0 + (r % DUPB);
        ((float4*)Ws)[e] = ((const float4*)(W2 + (size_t)grow*HID))[c4];
    }
    if (tid < 144) {
        int gi = tid / DUPB;
        int gg = (gi == 0) ? 0 : (gi == 1 ? 2 : 3);
        int grow = gg*HID + u0 + (tid % DUPB);
        bs[tid] = db1[grow] + db2[grow];
    }
    if (tid < 16) lbs[tid] = linb[f0 + tid];
    __syncthreads();

    for (int t = 0; t < TLEN; t++) {
        for (int e = tid; e < HID; e += 256) hbuf[e] = __ldcg(&g_hd[t&1][e]);
        __syncthreads();

        if (tid < 144) {
            float sum = 0.f;
            const float4* h4 = (const float4*)hbuf;
            if (tid < SROWS) {
                const float4* W4 = (const float4*)(Ws + tid*HID);
#pragma unroll 8
                for (int m = 0; m < HID/4; m++) {
                    float4 wv = W4[m]; float4 hv = h4[m];
                    sum += wv.x*hv.x + wv.y*hv.y + wv.z*hv.z + wv.w*hv.w;
                }
            } else {
                int gi = tid / DUPB;
                int gg = (gi == 1) ? 2 : 3;
                int grow = gg*HID + u0 + (tid % DUPB);
                const float4* W4 = (const float4*)(W2 + (size_t)grow*HID);
#pragma unroll 8
                for (int m = 0; m < HID/4; m++) {
                    float4 wv = __ldg(&W4[m]); float4 hv = h4[m];
                    sum += wv.x*hv.x + wv.y*hv.y + wv.z*hv.z + wv.w*hv.w;
                }
            }
            gs[tid] = sum + bs[tid];
        }
        __syncthreads();
        if (tid < DUPB) {
            float cn = sigf(gs[tid]) * tanhfast(gs[48 + tid]);
            float hn = sigf(gs[96 + tid]) * tanhfast(cn);
            __stcg(&g_hd[(t+1)&1][u0 + tid], hn);
        }
        __syncthreads();
        if (tid == 0) {
            bar_arrive(&g_bar2);
            unsigned target = (unsigned)(t + 1) * DNB;
            while (bar_poll(&g_bar2) < target) {}
        }
        __syncthreads();

        for (int e = tid; e < HID; e += 256) hbuf[e] = __ldcg(&g_hd[(t+1)&1][e]);
        __syncthreads();
        {
            int fl = tid >> 4, s = tid & 15;
            const float4* W4 = (const float4*)(linW + (size_t)(f0 + fl)*HID);
            const float4* h4 = (const float4*)hbuf;
            float p = 0.f;
#pragma unroll
            for (int m = 0; m < 12; m++) {
                float4 wv = __ldg(&W4[s + 16*m]); float4 hv = h4[s + 16*m];
                p += wv.x*hv.x + wv.y*hv.y + wv.z*hv.z + wv.w*hv.w;
            }
#pragma unroll
            for (int off = 8; off > 0; off >>= 1)
                p += __shfl_down_sync(0xffffffffu, p, off, 16);
            if (s == 0) osv[fl] = p + lbs[fl];
        }
        __syncthreads();
        for (int e = tid; e < BATCH*16; e += 256) {
            int b = e >> 4, fl = e & 15;
            out[(size_t)t*BATCH*FEAT + b*FEAT + f0 + fl] = osv[fl];
        }
        __syncthreads();
    }
}

__global__ __launch_bounds__(256) void k_encdec(
    const float* __restrict__ Whh, const float* __restrict__ eWih,
    const float* __restrict__ ebih, const float* __restrict__ ebhh,
    const float* __restrict__ W2, const float* __restrict__ db1,
    const float* __restrict__ db2, const float* __restrict__ linW,
    const float* __restrict__ linb, float* __restrict__ out)
{
    extern __shared__ char smraw[];
    if (blockIdx.x < NB)
        enc_path(Whh, eWih, ebih, ebhh, out, smraw);
    else
        dec_path(W2, db1, db2, linW, linb, out, smraw);
}

extern "C" void kernel_launch(void* const* d_in, const int* in_sizes, int n_in,
                              void* d_out, int out_size)
{
    const float* x     = (const float*)d_in[0];
    const float* Wih0  = (const float*)d_in[1];
    const float* Whh0  = (const float*)d_in[2];
    const float* bih0  = (const float*)d_in[3];
    const float* bhh0  = (const float*)d_in[4];
    const float* eWih  = (const float*)d_in[5];
    const float* ebih  = (const float*)d_in[7];
    const float* ebhh  = (const float*)d_in[8];
    const float* dWih  = (const float*)d_in[9];
    const float* dbih  = (const float*)d_in[11];
    const float* dbhh  = (const float*)d_in[12];
    const float* linW  = (const float*)d_in[13];
    const float* linb  = (const float*)d_in[14];
    float* out = (float*)d_out;

    // enc layout: 37248 (W hi) + 98304 (h) + 12672 (gates) + 1536 (c) = 149760 B
    // dec layout: 225536 B -> request max
    const int fused_smem = (SROWS*HID + HID + 144 + 144 + 16 + 16) * 4;
    const int xg_smem  = 65536 + 132*4;

    static int smem_set = 0;
    if (!smem_set) {
        cudaFuncSetAttribute(k_encdec, cudaFuncAttributeMaxDynamicSharedMemorySize, fused_smem);
        cudaFuncSetAttribute(k_xg_mma, cudaFuncAttributeMaxDynamicSharedMemorySize, xg_smem);
        smem_set = 1;
    }

    k_prep<<<(XM*FEAT + 511)/512, 512>>>(x, Wih0);
    k_xg_mma<<<dim3(24, 128), 256, xg_smem>>>(bih0, bhh0);

    k_encdec<<<NB + DNB, 256, fused_smem>>>(
        Whh0, eWih, ebih, ebhh,
        dWih + (size_t)2 * GATES * HID, dbih + 2 * GATES, dbhh + 2 * GATES,
        linW, linb, out);
}

// round 16
// speedup vs baseline: 1.5669x; 1.0030x over previous
#include <cuda_runtime.h>
#include <cuda_fp16.h>
#include <math.h>
#include <stdint.h>

#define S_LEN 256
#define BATCH 64
#define FEAT  256
#define HID   768
#define GATES 3072
#define TLEN  32
#define OUT_ENC_OFF (TLEN*BATCH*FEAT)
#define XM    (S_LEN*BATCH)

#define NB   128      // encoder blocks
#define DNB  16       // decoder blocks (fused: blockIdx 128..143)
#define DUPB 48
#define SROWS 72
#define UPB  6
#define RPB  24
#define WPAD 776

// xg stored TRANSPOSED: [t][gate_row][batch]
static __device__ float g_xg[(size_t)S_LEN*GATES*BATCH];
static __device__ __half g_xh[(size_t)XM*FEAT];
static __device__ __half g_whi[(size_t)GATES*FEAT];
static __device__ __half g_hh[2][BATCH*HID];
static __device__ float g_hd[2][HID];
static __device__ unsigned g_bar;
static __device__ unsigned g_bar2;

__device__ __forceinline__ float sigf(float x){
    return __fdividef(1.f, 1.f + __expf(-x));
}
__device__ __forceinline__ float tanhfast(float x){
    return 1.f - __fdividef(2.f, __expf(2.f*x) + 1.f);
}

__device__ __forceinline__ void mma_f16(float* c, const uint32_t* a, uint32_t b0, uint32_t b1){
    asm volatile(
        "mma.sync.aligned.m16n8k16.row.col.f32.f16.f16.f32 "
        "{%0,%1,%2,%3}, {%4,%5,%6,%7}, {%8,%9}, {%0,%1,%2,%3};"
        : "+f"(c[0]), "+f"(c[1]), "+f"(c[2]), "+f"(c[3])
        : "r"(a[0]), "r"(a[1]), "r"(a[2]), "r"(a[3]), "r"(b0), "r"(b1));
}
__device__ __forceinline__ void ldsm4(uint32_t* a, uint32_t addr){
    asm volatile("ldmatrix.sync.aligned.m8n8.x4.shared.b16 {%0,%1,%2,%3}, [%4];"
        : "=r"(a[0]), "=r"(a[1]), "=r"(a[2]), "=r"(a[3]) : "r"(addr));
}
__device__ __forceinline__ void bar_arrive(unsigned* p){
    asm volatile("red.release.gpu.global.add.u32 [%0], %1;" :: "l"(p), "r"(1u) : "memory");
}
__device__ __forceinline__ unsigned bar_poll(unsigned* p){
    unsigned v;
    asm volatile("ld.acquire.gpu.global.u32 %0, [%1];" : "=r"(v) : "l"(p) : "memory");
    return v;
}

// fused init + X conversion + W conversion (one launch, fp16 hi-only)
__global__ void k_prep(const float* __restrict__ x, const float* __restrict__ Wih0) {
    int i = blockIdx.x*blockDim.x + threadIdx.x;
    if (i < BATCH*HID/2) ((uint32_t*)g_hh[0])[i] = 0u;
    if (i < HID) g_hd[0][i] = 0.f;
    if (i == 0) { g_bar = 0u; g_bar2 = 0u; }
    if (i < XM*FEAT) g_xh[i] = __float2half(x[i]);
    if (i < GATES*FEAT) g_whi[i] = __float2half(Wih0[i]);
}

// ---------------- tensor-core xg GEMM (fp16 hi-only, ldsm-B 4-matrix) -----
__global__ __launch_bounds__(256, 3) void k_xg_mma(
    const float* __restrict__ b1, const float* __restrict__ b2)
{
    extern __shared__ char smraw[];
    uint32_t xs_base = (uint32_t)__cvta_generic_to_shared(smraw);     // 32KB
    uint32_t ws_base = xs_base + 32768;                               // 32KB (hi only)
    float* sbias = (float*)(smraw + 65536);

    const int tid  = threadIdx.x;
    const int wid  = tid >> 5;
    const int lane = tid & 31;
    const int mw   = wid & 3;
    const int nw   = wid >> 2;
    const int bn   = blockIdx.x * 128;
    const int bm   = blockIdx.y * 128;
    const int l4 = lane >> 2;
    const int l2 = lane & 3;
    const int r  = lane & 15;
    const int seg = lane >> 4;
    const int bmid = lane >> 3;
    const int brow = lane & 7;

    if (tid < 128) sbias[tid] = b1[bn+tid] + b2[bn+tid];

    float acc[2][8][4];
#pragma unroll
    for (int mt = 0; mt < 2; mt++)
#pragma unroll
        for (int nt = 0; nt < 8; nt++)
#pragma unroll
            for (int j = 0; j < 4; j++) acc[mt][nt][j] = 0.f;

    for (int ph = 0; ph < 2; ph++) {
        __syncthreads();
        // X: 2048 granules (8/thread)
#pragma unroll
        for (int i = 0; i < 8; i++) {
            int g = tid + i*256;
            int s = g & 15, row = g >> 4;
            uint32_t dst = xs_base + (uint32_t)(row*256 + ((s ^ (row&7))*16));
            const __half* src = g_xh + (size_t)(bm+row)*FEAT + ph*128 + s*8;
            asm volatile("cp.async.cg.shared.global [%0], [%1], 16;" :: "r"(dst), "l"(src));
        }
        // W hi: 2048 granules (8/thread)
#pragma unroll
        for (int i = 0; i < 8; i++) {
            int g = tid + i*256;
            int s = g & 15, row = g >> 4;
            uint32_t dst = ws_base + (uint32_t)(row*256 + ((s ^ (row&7))*16));
            const __half* src = g_whi + (size_t)(bn+row)*FEAT + ph*128 + s*8;
            asm volatile("cp.async.cg.shared.global [%0], [%1], 16;" :: "r"(dst), "l"(src));
        }
        asm volatile("cp.async.commit_group;");
        asm volatile("cp.async.wait_group 0;");
        __syncthreads();

#pragma unroll
        for (int ks2 = 0; ks2 < 4; ks2++) {
            uint32_t ahi[2][2][4];
#pragma unroll
            for (int mt = 0; mt < 2; mt++) {
                uint32_t rowoff = (uint32_t)((mw*32 + mt*16 + r)*256);
#pragma unroll
                for (int j = 0; j < 2; j++) {
                    uint32_t coff = (uint32_t)(((ks2*2 + j)*32 + seg*16) ^ ((r&7)*16));
                    ldsm4(ahi[mt][j], xs_base + rowoff + coff);
                }
            }
#pragma unroll
            for (int nt = 0; nt < 8; nt++) {
                // one ldsm4: matrices {k, k+8, k+16, k+24} for this nt
                int wrow = nw*64 + nt*8 + brow;
                uint32_t baddr = ws_base + (uint32_t)(wrow*256
                                 + (((ks2*4 + bmid) ^ brow)*16));
                uint32_t bf[4];
                ldsm4(bf, baddr);
#pragma unroll
                for (int mt = 0; mt < 2; mt++) {
                    mma_f16(acc[mt][nt], ahi[mt][0], bf[0], bf[1]);
                    mma_f16(acc[mt][nt], ahi[mt][1], bf[2], bf[3]);
                }
            }
        }
    }

#pragma unroll
    for (int mt = 0; mt < 2; mt++) {
#pragma unroll
        for (int nt = 0; nt < 8; nt++) {
            int nloc = nw*64 + nt*8 + 2*l2;
            int n0 = bn + nloc;
            int m0 = bm + mw*32 + mt*16 + l4;
            int t = m0 >> 6, b = m0 & 63;
            size_t base = (size_t)t*GATES*BATCH;
            float bi0 = sbias[nloc], bi1 = sbias[nloc+1];
            g_xg[base + (size_t)n0*BATCH + b]         = acc[mt][nt][0] + bi0;
            g_xg[base + (size_t)(n0+1)*BATCH + b]     = acc[mt][nt][1] + bi1;
            g_xg[base + (size_t)n0*BATCH + b + 8]     = acc[mt][nt][2] + bi0;
            g_xg[base + (size_t)(n0+1)*BATCH + b + 8] = acc[mt][nt][3] + bi1;
        }
    }
}

// ---------------- fused persistent kernel: encoder (blocks 0..127) +
//                  decoder (blocks 128..143, independent, overlapped) ------
__device__ __forceinline__ void load_xv(int t, int kh, int bx0,
                                        const int growx[3][2], float xv[3][2][2],
                                        const float* __restrict__ eb1,
                                        const float* __restrict__ eb2)
{
    if (kh != 0 || t >= 258) return;
    if (t < 256) {
        const float* xg = g_xg + (size_t)t * GATES * BATCH;
#pragma unroll
        for (int nt = 0; nt < 3; nt++)
#pragma unroll
            for (int jj = 0; jj < 2; jj++) {
                const float* rowp = xg + (size_t)growx[nt][jj]*BATCH + bx0;
                xv[nt][jj][0] = __ldcg(rowp);
                xv[nt][jj][1] = __ldcg(rowp + 8);
            }
    } else {
        int l = t - 256;
#pragma unroll
        for (int nt = 0; nt < 3; nt++)
#pragma unroll
            for (int jj = 0; jj < 2; jj++) {
                float bb = __ldg(eb1 + l*GATES + growx[nt][jj]) +
                           __ldg(eb2 + l*GATES + growx[nt][jj]);
                xv[nt][jj][0] = bb;
                xv[nt][jj][1] = bb;
            }
    }
}

__device__ void enc_path(
    const float* __restrict__ Whh, const float* __restrict__ eWih,
    const float* __restrict__ ebih, const float* __restrict__ ebhh,
    float* __restrict__ out, char* smraw)
{
    __half* Whi = (__half*)smraw;                      // 24*776 (hi only)
    __half* hsm = Whi + RPB*WPAD;                      // 6 subtiles * 16KB
    float* gA  = (float*)((char*)hsm + 98304);
    float* gB  = gA + RPB*66;
    float* c_s = gB + RPB*66;

    const int tid  = threadIdx.x;
    const int wid  = tid >> 5;
    const int lane = tid & 31;
    const int mw   = wid & 3;
    const int kh   = wid >> 2;
    const int u0   = blockIdx.x * UPB;

    for (int e = tid; e < RPB*HID; e += 256) {
        int rr = e / HID, k = e % HID;
        int grow = (rr/UPB)*HID + u0 + (rr%UPB);
        Whi[rr*WPAD + k] = __float2half(Whh[(size_t)grow*HID + k]);
    }
    for (int e = tid; e < UPB*BATCH; e += 256) c_s[e] = 0.f;

    uint32_t hs_base = (uint32_t)__cvta_generic_to_shared(hsm);

    const int l4 = lane >> 2;
    const int l2 = lane & 3;
    const int bmid = lane >> 3;
    const int brow = lane & 7;
    // B ldsm base: row brow (within nt tile), matrix bmid -> col byte +16*bmid
    uint32_t wsmB = (uint32_t)__cvta_generic_to_shared(Whi + (size_t)brow*WPAD)
                    + (uint32_t)(bmid * 16);

    int growx[3][2];
#pragma unroll
    for (int nt = 0; nt < 3; nt++)
#pragma unroll
        for (int jj = 0; jj < 2; jj++) {
            int row = nt*8 + 2*l2 + jj;
            growx[nt][jj] = (row/UPB)*HID + u0 + (row%UPB);
        }
    const int bx0 = 16*mw + l4;

    float xv[3][2][2];
    load_xv(0, kh, bx0, growx, xv, ebih, ebhh);

    __syncthreads();

    for (int t = 0; t < 258; t++) {
        if (t >= 256) {
            const float* Wsrc = eWih + (size_t)(t - 256) * GATES * HID;
            for (int e = tid; e < RPB*HID; e += 256) {
                int rr = e / HID, k = e % HID;
                int grow = (rr/UPB)*HID + u0 + (rr%UPB);
                Whi[rr*WPAD + k] = __float2half(Wsrc[(size_t)grow*HID + k]);
            }
            __syncthreads();
        }

        const __half* hh = g_hh[t & 1];

        // stage full h (96KB) in one volley
#pragma unroll
        for (int i = 0; i < 24; i++) {
            int g = tid + i*256;
            int s = g & 15, b = (g >> 4) & 63, c = g >> 10;
            uint32_t dst = hs_base + (uint32_t)(c*16384 + b*256 + ((s ^ (b&7))*16));
            const __half* src = hh + (size_t)b*HID + c*128 + s*8;
            asm volatile("cp.async.cg.shared.global [%0], [%1], 16;" :: "r"(dst), "l"(src));
        }
        asm volatile("cp.async.commit_group;");
        asm volatile("cp.async.wait_group 0;");
        __syncthreads();

        float acc[3][4];
#pragma unroll
        for (int nt = 0; nt < 3; nt++)
#pragma unroll
            for (int j = 0; j < 4; j++) acc[nt][j] = 0.f;

        const int rr = lane & 15, sg = lane >> 4;
        const uint32_t rowoff = (uint32_t)((16*mw + rr)*256);
        const uint32_t swz = (uint32_t)((rr&7)*16);
#pragma unroll
        for (int p = 0; p < 3; p++) {
            const int c = 3*kh + p;
            uint32_t subb = hs_base + (uint32_t)(c*16384);
            uint32_t kbyte0 = (uint32_t)(c*256);
#pragma unroll
            for (int ks2 = 0; ks2 < 4; ks2++) {
                uint32_t a0[4], a1[4];
                uint32_t coff0 = (uint32_t)((ks2*2  )*32 + sg*16) ^ swz;
                uint32_t coff1 = (uint32_t)((ks2*2+1)*32 + sg*16) ^ swz;
                ldsm4(a0, subb + rowoff + coff0);
                ldsm4(a1, subb + rowoff + coff1);
                uint32_t kb = kbyte0 + (uint32_t)(ks2*64);
#pragma unroll
                for (int nt = 0; nt < 3; nt++) {
                    uint32_t bf[4];
                    ldsm4(bf, wsmB + (uint32_t)(nt*8*WPAD*2) + kb);
                    mma_f16(acc[nt], a0, bf[0], bf[1]);
                    mma_f16(acc[nt], a1, bf[2], bf[3]);
                }
            }
        }

        float* dst = kh ? gB : gA;
#pragma unroll
        for (int nt = 0; nt < 3; nt++) {
            int r0 = nt*8 + 2*l2;
            if (kh == 0) {
                dst[(r0  )*66 + bx0    ] = acc[nt][0] + xv[nt][0][0];
                dst[(r0+1)*66 + bx0    ] = acc[nt][1] + xv[nt][1][0];
                dst[(r0  )*66 + bx0 + 8] = acc[nt][2] + xv[nt][0][1];
                dst[(r0+1)*66 + bx0 + 8] = acc[nt][3] + xv[nt][1][1];
            } else {
                dst[(r0  )*66 + bx0    ] = acc[nt][0];
                dst[(r0+1)*66 + bx0    ] = acc[nt][1];
                dst[(r0  )*66 + bx0 + 8] = acc[nt][2];
                dst[(r0+1)*66 + bx0 + 8] = acc[nt][3];
            }
        }
        __syncthreads();

        __half* oh = g_hh[(t+1)&1];
        for (int e = tid; e < UPB*BATCH; e += 256) {
            int u = e % UPB, b = e / UPB;
            float iv = gA[(u)       *66 + b] + gB[(u)       *66 + b];
            float fv = gA[(UPB  +u) *66 + b] + gB[(UPB  +u) *66 + b];
            float gv = gA[(2*UPB+u) *66 + b] + gB[(2*UPB+u) *66 + b];
            float ov = gA[(3*UPB+u) *66 + b] + gB[(3*UPB+u) *66 + b];
            float cn, hn;
            if (t < 256) {
                float cp = c_s[e];
                cn = sigf(fv) * cp + sigf(iv) * tanhfast(gv);
                c_s[e] = cn;
            } else {
                cn = sigf(iv) * tanhfast(gv);
            }
            hn = sigf(ov) * tanhfast(cn);
            int idx = b*HID + u0 + u;
            oh[idx] = __float2half(hn);
            if (t == 255) out[OUT_ENC_OFF + idx] = hn;
            else if (t == 256) out[OUT_ENC_OFF + BATCH*HID + idx] = hn;
            else if (t == 257) out[OUT_ENC_OFF + 2*BATCH*HID + idx] = hn;
        }

        __syncthreads();
        if (tid == 0) bar_arrive(&g_bar);
        load_xv(t + 1, kh, bx0, growx, xv, ebih, ebhh);
        if (tid == 0) {
            unsigned target = (unsigned)(t + 1) * NB;
            while (bar_poll(&g_bar) < target) {}
        }
        __syncthreads();
    }
}

// decoder path: 16 blocks, 48 units each; gate rows {i,g,o} = 144/block.
__device__ void dec_path(
    const float* __restrict__ W2, const float* __restrict__ db1,
    const float* __restrict__ db2, const float* __restrict__ linW,
    const float* __restrict__ linb, float* __restrict__ out, char* smraw)
{
    float* Ws   = (float*)smraw;
    float* hbuf = Ws + SROWS*HID;
    float* gs   = hbuf + HID;
    float* bs   = gs + 144;
    float* osv  = bs + 144;
    float* lbs  = osv + 16;

    const int tid = threadIdx.x;
    const int blk = blockIdx.x - NB;
    const int u0 = blk * DUPB;
    const int f0 = blk * 16;

    for (int e = tid; e < SROWS*(HID/4); e += 256) {
        int r = e / (HID/4), c4 = e % (HID/4);
        int gi = r / DUPB;
        int grow = (gi == 0 ? 0 : 2)*HID + u0 + (r % DUPB);
        ((float4*)Ws)[e] = ((const float4*)(W2 + (size_t)grow*HID))[c4];
    }
    if (tid < 144) {
        int gi = tid / DUPB;
        int gg = (gi == 0) ? 0 : (gi == 1 ? 2 : 3);
        int grow = gg*HID + u0 + (tid % DUPB);
        bs[tid] = db1[grow] + db2[grow];
    }
    if (tid < 16) lbs[tid] = linb[f0 + tid];
    __syncthreads();

    for (int t = 0; t < TLEN; t++) {
        for (int e = tid; e < HID; e += 256) hbuf[e] = __ldcg(&g_hd[t&1][e]);
        __syncthreads();

        if (tid < 144) {
            float sum = 0.f;
            const float4* h4 = (const float4*)hbuf;
            if (tid < SROWS) {
                const float4* W4 = (const float4*)(Ws + tid*HID);
#pragma unroll 8
                for (int m = 0; m < HID/4; m++) {
                    float4 wv = W4[m]; float4 hv = h4[m];
                    sum += wv.x*hv.x + wv.y*hv.y + wv.z*hv.z + wv.w*hv.w;
                }
            } else {
                int gi = tid / DUPB;
                int gg = (gi == 1) ? 2 : 3;
                int grow = gg*HID + u0 + (tid % DUPB);
                const float4* W4 = (const float4*)(W2 + (size_t)grow*HID);
#pragma unroll 8
                for (int m = 0; m < HID/4; m++) {
                    float4 wv = __ldg(&W4[m]); float4 hv = h4[m];
                    sum += wv.x*hv.x + wv.y*hv.y + wv.z*hv.z + wv.w*hv.w;
                }
            }
            gs[tid] = sum + bs[tid];
        }
        __syncthreads();
        if (tid < DUPB) {
            float cn = sigf(gs[tid]) * tanhfast(gs[48 + tid]);
            float hn = sigf(gs[96 + tid]) * tanhfast(cn);
            __stcg(&g_hd[(t+1)&1][u0 + tid], hn);
        }
        __syncthreads();
        if (tid == 0) {
            bar_arrive(&g_bar2);
            unsigned target = (unsigned)(t + 1) * DNB;
            while (bar_poll(&g_bar2) < target) {}
        }
        __syncthreads();

        for (int e = tid; e < HID; e += 256) hbuf[e] = __ldcg(&g_hd[(t+1)&1][e]);
        __syncthreads();
        {
            int fl = tid >> 4, s = tid & 15;
            const float4* W4 = (const float4*)(linW + (size_t)(f0 + fl)*HID);
            const float4* h4 = (const float4*)hbuf;
            float p = 0.f;
#pragma unroll
            for (int m = 0; m < 12; m++) {
                float4 wv = __ldg(&W4[s + 16*m]); float4 hv = h4[s + 16*m];
                p += wv.x*hv.x + wv.y*hv.y + wv.z*hv.z + wv.w*hv.w;
            }
#pragma unroll
            for (int off = 8; off > 0; off >>= 1)
                p += __shfl_down_sync(0xffffffffu, p, off, 16);
            if (s == 0) osv[fl] = p + lbs[fl];
        }
        __syncthreads();
        for (int e = tid; e < BATCH*16; e += 256) {
            int b = e >> 4, fl = e & 15;
            out[(size_t)t*BATCH*FEAT + b*FEAT + f0 + fl] = osv[fl];
        }
        __syncthreads();
    }
}

__global__ __launch_bounds__(256) void k_encdec(
    const float* __restrict__ Whh, const float* __restrict__ eWih,
    const float* __restrict__ ebih, const float* __restrict__ ebhh,
    const float* __restrict__ W2, const float* __restrict__ db1,
    const float* __restrict__ db2, const float* __restrict__ linW,
    const float* __restrict__ linb, float* __restrict__ out)
{
    extern __shared__ char smraw[];
    if (blockIdx.x < NB)
        enc_path(Whh, eWih, ebih, ebhh, out, smraw);
    else
        dec_path(W2, db1, db2, linW, linb, out, smraw);
}

extern "C" void kernel_launch(void* const* d_in, const int* in_sizes, int n_in,
                              void* d_out, int out_size)
{
    const float* x     = (const float*)d_in[0];
    const float* Wih0  = (const float*)d_in[1];
    const float* Whh0  = (const float*)d_in[2];
    const float* bih0  = (const float*)d_in[3];
    const float* bhh0  = (const float*)d_in[4];
    const float* eWih  = (const float*)d_in[5];
    const float* ebih  = (const float*)d_in[7];
    const float* ebhh  = (const float*)d_in[8];
    const float* dWih  = (const float*)d_in[9];
    const float* dbih  = (const float*)d_in[11];
    const float* dbhh  = (const float*)d_in[12];
    const float* linW  = (const float*)d_in[13];
    const float* linb  = (const float*)d_in[14];
    float* out = (float*)d_out;

    // enc layout: 37248 (W hi) + 98304 (h) + 12672 (gates) + 1536 (c) = 149760 B
    // dec layout: 225536 B -> request max
    const int fused_smem = (SROWS*HID + HID + 144 + 144 + 16 + 16) * 4;
    const int xg_smem  = 65536 + 132*4;

    static int smem_set = 0;
    if (!smem_set) {
        cudaFuncSetAttribute(k_encdec, cudaFuncAttributeMaxDynamicSharedMemorySize, fused_smem);
        cudaFuncSetAttribute(k_xg_mma, cudaFuncAttributeMaxDynamicSharedMemorySize, xg_smem);
        smem_set = 1;
    }

    k_prep<<<(XM*FEAT + 511)/512, 512>>>(x, Wih0);
    k_xg_mma<<<dim3(24, 128), 256, xg_smem>>>(bih0, bhh0);

    k_encdec<<<NB + DNB, 256, fused_smem>>>(
        Whh0, eWih, ebih, ebhh,
        dWih + (size_t)2 * GATES * HID, dbih + 2 * GATES, dbhh + 2 * GATES,
        linW, linb, out);
}